// round 3
// baseline (speedup 1.0000x reference)
#include <cuda_runtime.h>
#include <cuda_bf16.h>
#include <stdint.h>

// Problem constants (shapes fixed by the dataset)
#define DN 50000     // nodes
#define DE 600000    // edges
#define DD 128       // feature dim
#define DR 8         // relations

// ---------------- scratch (device globals; no allocs allowed) ----------------
__device__ float g_xw[(size_t)DN * DR * DD];   // per-(node,rel) transformed feats, [n][r][d]
__device__ float g_h[(size_t)DN * DD];         // layer-1 output
__device__ float g_agg[(size_t)DN * DD];       // aggregation buffer
__device__ int   g_cnt[DN * DR];               // per-(dst,rel) edge counts
__device__ int   g_ndeg[DN];                   // per-dst edge counts
__device__ int   g_rowptr[DN + 1];             // CSR row pointers (by dst)
__device__ int   g_woff[DN];                   // working offsets for CSR scatter
__device__ int   g_ekey[DE];                   // per-edge src*R+et, CSR order
__device__ float g_ecoef[DE];                  // per-edge 1/max(cnt,1), CSR order

// ---------------- small utility kernels ----------------
__global__ void zero_ints_kernel() {
    int i = blockIdx.x * blockDim.x + threadIdx.x;
    int total = DN * DR + DN;
    for (; i < total; i += gridDim.x * blockDim.x) {
        if (i < DN * DR) g_cnt[i] = 0;
        else             g_ndeg[i - DN * DR] = 0;
    }
}

__global__ void count_kernel(const int* __restrict__ ei, const int* __restrict__ et, int E) {
    int e = blockIdx.x * blockDim.x + threadIdx.x;
    for (; e < E; e += gridDim.x * blockDim.x) {
        int d = ei[E + e];     // dst row of ei [2,E]
        int t = et[e];
        atomicAdd(&g_cnt[d * DR + t], 1);
        atomicAdd(&g_ndeg[d], 1);
    }
}

// single-block scan over g_ndeg -> g_rowptr (exclusive), g_woff (start offsets)
__global__ void scan_kernel(int N) {
    __shared__ int s[1024];
    __shared__ int carry_s;
    int tid = threadIdx.x;
    if (tid == 0) { carry_s = 0; g_rowptr[0] = 0; }
    __syncthreads();
    for (int base = 0; base < N; base += 1024) {
        int i = base + tid;
        int v = (i < N) ? g_ndeg[i] : 0;
        s[tid] = v;
        __syncthreads();
        // Hillis-Steele inclusive scan
        for (int off = 1; off < 1024; off <<= 1) {
            int t = (tid >= off) ? s[tid - off] : 0;
            __syncthreads();
            s[tid] += t;
            __syncthreads();
        }
        int incl = s[tid];
        int carry = carry_s;
        if (i < N) {
            g_rowptr[i + 1] = carry + incl;
            g_woff[i]       = carry + incl - v;
        }
        __syncthreads();
        if (tid == 1023) carry_s = carry + incl;
        __syncthreads();
    }
}

__global__ void scatter_kernel(const int* __restrict__ ei, const int* __restrict__ et, int E) {
    int e = blockIdx.x * blockDim.x + threadIdx.x;
    for (; e < E; e += gridDim.x * blockDim.x) {
        int s = ei[e];
        int d = ei[E + e];
        int t = et[e];
        int pos = atomicAdd(&g_woff[d], 1);
        g_ekey[pos]  = s * DR + t;
        int c = g_cnt[d * DR + t];
        g_ecoef[pos] = 1.0f / (float)(c > 0 ? c : 1);
    }
}

__global__ void copy_rel_kernel(const float* __restrict__ rel, float* __restrict__ out, int n) {
    int i = blockIdx.x * blockDim.x + threadIdx.x;
    if (i < n) out[i] = rel[i];
}

// ---------------- GEMM: xw[n][r][:] = x[n] @ W[r] ----------------
// BM=128 nodes x BN=128 outputs, BK=16, 256 threads, 8x8 thread tile.
__global__ __launch_bounds__(256) void gemm_xw_kernel(
    const float* __restrict__ X, const float* __restrict__ W,
    float* __restrict__ out, int N)
{
    __shared__ float As[16][128];   // [k][m]
    __shared__ float Bs[16][128];   // [k][n]
    const int r  = blockIdx.y;
    const int m0 = blockIdx.x * 128;
    const float* Wr = W + (size_t)r * DD * DD;
    const int tid = threadIdx.x;
    const int tx = tid & 15;   // output-col tile
    const int ty = tid >> 4;   // node-row tile

    float acc[8][8];
    #pragma unroll
    for (int i = 0; i < 8; i++)
        #pragma unroll
        for (int j = 0; j < 8; j++) acc[i][j] = 0.0f;

    const int aRow = tid >> 2;          // 0..63
    const int aCol = (tid & 3) * 4;     // 0,4,8,12
    const int bRow = tid >> 5;          // 0..7
    const int bCol = (tid & 31) * 4;    // 0..124

    for (int k0 = 0; k0 < DD; k0 += 16) {
        #pragma unroll
        for (int i = 0; i < 2; i++) {
            int m = m0 + aRow + i * 64;
            float4 v = make_float4(0.f, 0.f, 0.f, 0.f);
            if (m < N) v = *(const float4*)(X + (size_t)m * DD + k0 + aCol);
            As[aCol + 0][aRow + i * 64] = v.x;
            As[aCol + 1][aRow + i * 64] = v.y;
            As[aCol + 2][aRow + i * 64] = v.z;
            As[aCol + 3][aRow + i * 64] = v.w;
        }
        #pragma unroll
        for (int i = 0; i < 2; i++) {
            int kk = bRow + i * 8;
            *(float4*)&Bs[kk][bCol] = *(const float4*)(Wr + (size_t)(k0 + kk) * DD + bCol);
        }
        __syncthreads();
        #pragma unroll
        for (int k = 0; k < 16; k++) {
            float4 a0 = *(const float4*)&As[k][ty * 8];
            float4 a1 = *(const float4*)&As[k][ty * 8 + 4];
            float4 b0 = *(const float4*)&Bs[k][tx * 8];
            float4 b1 = *(const float4*)&Bs[k][tx * 8 + 4];
            float a[8] = {a0.x,a0.y,a0.z,a0.w,a1.x,a1.y,a1.z,a1.w};
            float b[8] = {b0.x,b0.y,b0.z,b0.w,b1.x,b1.y,b1.z,b1.w};
            #pragma unroll
            for (int i = 0; i < 8; i++)
                #pragma unroll
                for (int j = 0; j < 8; j++) acc[i][j] += a[i] * b[j];
        }
        __syncthreads();
    }
    #pragma unroll
    for (int i = 0; i < 8; i++) {
        int m = m0 + ty * 8 + i;
        if (m < N) {
            float* dst = out + ((size_t)m * DR + r) * DD + tx * 8;
            *(float4*)(dst)     = make_float4(acc[i][0], acc[i][1], acc[i][2], acc[i][3]);
            *(float4*)(dst + 4) = make_float4(acc[i][4], acc[i][5], acc[i][6], acc[i][7]);
        }
    }
}

// ---------------- aggregation: warp per node, CSR gather ----------------
__global__ void agg_kernel(const float* __restrict__ xw, float* __restrict__ agg, int N) {
    int warp = (blockIdx.x * blockDim.x + threadIdx.x) >> 5;
    int lane = threadIdx.x & 31;
    if (warp >= N) return;
    int beg = g_rowptr[warp];
    int end = g_rowptr[warp + 1];
    float4 acc = make_float4(0.f, 0.f, 0.f, 0.f);
    for (int e = beg; e < end; e++) {
        int key = g_ekey[e];
        float c = g_ecoef[e];
        float4 v = *(const float4*)(xw + (size_t)key * DD + lane * 4);
        acc.x += c * v.x; acc.y += c * v.y; acc.z += c * v.z; acc.w += c * v.w;
    }
    *(float4*)(agg + (size_t)warp * DD + lane * 4) = acc;
}

// ---------------- root GEMM + bias + agg + relu: h = relu(x@root + b + agg) ----
__global__ __launch_bounds__(256) void root_relu_kernel(
    const float* __restrict__ X, const float* __restrict__ Wroot,
    const float* __restrict__ bias, const float* __restrict__ agg,
    float* __restrict__ out, int N)
{
    __shared__ float As[16][128];
    __shared__ float Bs[16][128];
    const int m0 = blockIdx.x * 128;
    const int tid = threadIdx.x;
    const int tx = tid & 15;
    const int ty = tid >> 4;

    float acc[8][8];
    #pragma unroll
    for (int i = 0; i < 8; i++)
        #pragma unroll
        for (int j = 0; j < 8; j++) acc[i][j] = 0.0f;

    const int aRow = tid >> 2;
    const int aCol = (tid & 3) * 4;
    const int bRow = tid >> 5;
    const int bCol = (tid & 31) * 4;

    for (int k0 = 0; k0 < DD; k0 += 16) {
        #pragma unroll
        for (int i = 0; i < 2; i++) {
            int m = m0 + aRow + i * 64;
            float4 v = make_float4(0.f, 0.f, 0.f, 0.f);
            if (m < N) v = *(const float4*)(X + (size_t)m * DD + k0 + aCol);
            As[aCol + 0][aRow + i * 64] = v.x;
            As[aCol + 1][aRow + i * 64] = v.y;
            As[aCol + 2][aRow + i * 64] = v.z;
            As[aCol + 3][aRow + i * 64] = v.w;
        }
        #pragma unroll
        for (int i = 0; i < 2; i++) {
            int kk = bRow + i * 8;
            *(float4*)&Bs[kk][bCol] = *(const float4*)(Wroot + (size_t)(k0 + kk) * DD + bCol);
        }
        __syncthreads();
        #pragma unroll
        for (int k = 0; k < 16; k++) {
            float4 a0 = *(const float4*)&As[k][ty * 8];
            float4 a1 = *(const float4*)&As[k][ty * 8 + 4];
            float4 b0 = *(const float4*)&Bs[k][tx * 8];
            float4 b1 = *(const float4*)&Bs[k][tx * 8 + 4];
            float a[8] = {a0.x,a0.y,a0.z,a0.w,a1.x,a1.y,a1.z,a1.w};
            float b[8] = {b0.x,b0.y,b0.z,b0.w,b1.x,b1.y,b1.z,b1.w};
            #pragma unroll
            for (int i = 0; i < 8; i++)
                #pragma unroll
                for (int j = 0; j < 8; j++) acc[i][j] += a[i] * b[j];
        }
        __syncthreads();
    }
    #pragma unroll
    for (int i = 0; i < 8; i++) {
        int m = m0 + ty * 8 + i;
        if (m < N) {
            const float* ag = agg + (size_t)m * DD + tx * 8;
            float* dst = out + (size_t)m * DD + tx * 8;
            #pragma unroll
            for (int j = 0; j < 8; j++) {
                float v = acc[i][j] + ag[j] + bias[tx * 8 + j];
                dst[j] = v > 0.f ? v : 0.f;
            }
        }
    }
}

// ---------------- launch ----------------
extern "C" void kernel_launch(void* const* d_in, const int* in_sizes, int n_in,
                              void* d_out, int out_size) {
    const float* x     = (const float*)d_in[0];
    const int*   ei    = (const int*)d_in[1];
    const int*   et    = (const int*)d_in[2];
    const float* W1    = (const float*)d_in[3];
    const float* root1 = (const float*)d_in[4];
    const float* b1    = (const float*)d_in[5];
    const float* W2    = (const float*)d_in[6];
    const float* root2 = (const float*)d_in[7];
    const float* b2    = (const float*)d_in[8];
    const float* rel   = (const float*)d_in[9];

    const int N = in_sizes[0] / DD;   // 50000
    const int E = in_sizes[2];        // 600000

    float* xw;   cudaGetSymbolAddress((void**)&xw,  g_xw);
    float* h1;   cudaGetSymbolAddress((void**)&h1,  g_h);
    float* agg;  cudaGetSymbolAddress((void**)&agg, g_agg);

    float* out_h   = (float*)d_out;                       // [N, D]
    float* out_rel = (float*)d_out + (size_t)N * DD;      // [R, D]

    // ---- preprocessing: counts, CSR (int atomics only) ----
    zero_ints_kernel<<<256, 256>>>();
    count_kernel<<<(E + 255) / 256, 256>>>(ei, et, E);
    scan_kernel<<<1, 1024>>>(N);
    scatter_kernel<<<(E + 255) / 256, 256>>>(ei, et, E);

    dim3 gemm_grid((N + 127) / 128, DR);
    dim3 root_grid((N + 127) / 128);
    int  agg_blocks = (N * 32 + 255) / 256;

    // ---- layer 1 ----
    gemm_xw_kernel<<<gemm_grid, 256>>>(x, W1, xw, N);
    agg_kernel<<<agg_blocks, 256>>>(xw, agg, N);
    root_relu_kernel<<<root_grid, 256>>>(x, root1, b1, agg, h1, N);

    // ---- layer 2 (writes into d_out) ----
    gemm_xw_kernel<<<gemm_grid, 256>>>(h1, W2, xw, N);
    agg_kernel<<<agg_blocks, 256>>>(xw, agg, N);
    root_relu_kernel<<<root_grid, 256>>>(h1, root2, b2, agg, out_h, N);

    // ---- append rel_emb ----
    copy_rel_kernel<<<1, 1024>>>(rel, out_rel, DR * DD);
}

// round 5
// speedup vs baseline: 1.5242x; 1.5242x over previous
#include <cuda_runtime.h>
#include <cuda_bf16.h>
#include <stdint.h>

// Problem constants (fixed by dataset)
#define DN 50000     // nodes
#define DE 600000    // edges
#define DD 128       // feature dim
#define DR 8         // relations
#define NR (DN * DR) // 400000 (dst,rel) segments
#define NCHUNK 9     // 8 relations + root
#define FULLM 0xffffffffu

// ---------------- scratch (device globals; no allocs allowed) ----------------
__device__ int   g_cnt[NR];              // per-(dst,rel) edge counts
__device__ int   g_rowptr2[NR + 1];      // CSR row pointers by (dst,rel)
__device__ int   g_woff[NR];             // working offsets for scatter
__device__ float g_coef[NR];             // 1/max(cnt,1) per (dst,rel)
__device__ int   g_esrc[DE];             // per-edge src index, CSR order
__device__ int   g_bsum[512];            // scan block sums
__device__ int   g_boff[512];            // scan block offsets
__device__ float g_h[(size_t)DN * DD];   // layer-1 output
// weight tiles, bf16 hi/lo, transposed layout [layer][chunk][n][k]
__device__ __nv_bfloat16 g_wbh[2 * NCHUNK * DD * DD];
__device__ __nv_bfloat16 g_wbl[2 * NCHUNK * DD * DD];

// ---------------- preprocessing kernels ----------------
__global__ void zero_cnt_kernel() {
    int i = blockIdx.x * blockDim.x + threadIdx.x;
    if (i < NR) g_cnt[i] = 0;
}

__global__ void count_kernel(const int* __restrict__ ei, const int* __restrict__ et, int E) {
    int e = blockIdx.x * blockDim.x + threadIdx.x;
    if (e < E) {
        int d = ei[E + e];
        int t = et[e];
        atomicAdd(&g_cnt[d * DR + t], 1);
    }
}

// level-1 scan: each block scans 1024 counts, writes exclusive prefixes + block sum
__global__ void scanA_kernel() {
    __shared__ int s[1024];
    int tid = threadIdx.x;
    int i = blockIdx.x * 1024 + tid;
    int v = (i < NR) ? g_cnt[i] : 0;
    s[tid] = v;
    __syncthreads();
    for (int off = 1; off < 1024; off <<= 1) {
        int t = (tid >= off) ? s[tid - off] : 0;
        __syncthreads();
        s[tid] += t;
        __syncthreads();
    }
    if (i < NR) g_rowptr2[i] = s[tid] - v;   // block-local exclusive
    if (tid == 1023) g_bsum[blockIdx.x] = s[1023];
}

// level-2 scan over block sums (nb <= 512)
__global__ void scanB_kernel(int nb) {
    __shared__ int s[512];
    int tid = threadIdx.x;
    int v = (tid < nb) ? g_bsum[tid] : 0;
    s[tid] = v;
    __syncthreads();
    for (int off = 1; off < 512; off <<= 1) {
        int t = (tid >= off) ? s[tid - off] : 0;
        __syncthreads();
        s[tid] += t;
        __syncthreads();
    }
    g_boff[tid] = s[tid] - v;   // exclusive
}

// finalize rowptr2, woff, coef
__global__ void scanC_kernel(int E) {
    int i = blockIdx.x * blockDim.x + threadIdx.x;
    if (i < NR) {
        int st = g_rowptr2[i] + g_boff[i >> 10];
        g_rowptr2[i] = st;
        g_woff[i] = st;
        int c = g_cnt[i];
        g_coef[i] = 1.0f / (float)(c > 0 ? c : 1);
        if (i == 0) g_rowptr2[NR] = E;
    }
}

__global__ void scatter_kernel(const int* __restrict__ ei, const int* __restrict__ et, int E) {
    int e = blockIdx.x * blockDim.x + threadIdx.x;
    if (e < E) {
        int s = ei[e];
        int d = ei[E + e];
        int t = et[e];
        int pos = atomicAdd(&g_woff[d * DR + t], 1);
        g_esrc[pos] = s;
    }
}

// convert + transpose weights into bf16 hi/lo tiles: g_wb[l][ch][n][k]
__global__ void wprep_kernel(const float* __restrict__ W1, const float* __restrict__ r1,
                             const float* __restrict__ W2, const float* __restrict__ r2) {
    int id = blockIdx.x * blockDim.x + threadIdx.x;
    const int total = 2 * NCHUNK * DD * DD;
    if (id >= total) return;
    int l   = id / (NCHUNK * DD * DD);
    int rem = id % (NCHUNK * DD * DD);
    int ch  = rem / (DD * DD);
    int pos = rem % (DD * DD);
    int n = pos >> 7, k = pos & 127;
    const float* W  = l ? W2 : W1;
    const float* rt = l ? r2 : r1;
    float wv = (ch < 8) ? W[((size_t)ch * DD + k) * DD + n] : rt[(size_t)k * DD + n];
    __nv_bfloat16 hi = __float2bfloat16(wv);
    float lo = wv - __bfloat162float(hi);
    g_wbh[id] = hi;
    g_wbl[id] = __float2bfloat16(lo);
}

__global__ void copy_rel_kernel(const float* __restrict__ rel, float* __restrict__ out, int n) {
    int i = blockIdx.x * blockDim.x + threadIdx.x;
    if (i < n) out[i] = rel[i];
}

// ---------------- fused RGCN layer ----------------
// One block = 128 dst nodes. For each of 9 K-chunks (8 relations + root):
//   gather per-(node,rel) mean of X rows into smem (bf16 hi/lo),
//   load weight tile (bf16 hi/lo, [n][k]),
//   accumulate 3-pass split-bf16 mma.sync into fp32 C.
// Epilogue: + bias, ReLU, write out.

__device__ __forceinline__ void mma_bf16(float c[4],
    uint32_t a0, uint32_t a1, uint32_t a2, uint32_t a3,
    uint32_t b0, uint32_t b1)
{
    asm volatile(
        "mma.sync.aligned.m16n8k16.row.col.f32.bf16.bf16.f32 "
        "{%0,%1,%2,%3}, {%4,%5,%6,%7}, {%8,%9}, {%0,%1,%2,%3};\n"
        : "+f"(c[0]), "+f"(c[1]), "+f"(c[2]), "+f"(c[3])
        : "r"(a0), "r"(a1), "r"(a2), "r"(a3), "r"(b0), "r"(b1));
}

#define APAD 136  // row stride in bf16 elems (conflict-free frag loads)
#define SMEM_BYTES (4 * 128 * APAD * 2)  // As_hi, As_lo, Bs_hi, Bs_lo

__global__ __launch_bounds__(256, 1) void fused_layer_kernel(
    const float* __restrict__ X,
    const __nv_bfloat16* __restrict__ WBH,   // offset to layer base
    const __nv_bfloat16* __restrict__ WBL,
    const float* __restrict__ bias,
    float* __restrict__ out, int N)
{
    extern __shared__ char smem[];
    __nv_bfloat16* As_hi = (__nv_bfloat16*)smem;
    __nv_bfloat16* As_lo = As_hi + 128 * APAD;
    __nv_bfloat16* Bs_hi = As_lo + 128 * APAD;
    __nv_bfloat16* Bs_lo = Bs_hi + 128 * APAD;

    const int tid  = threadIdx.x;
    const int w    = tid >> 5;
    const int lane = tid & 31;
    const int m0   = blockIdx.x * 128;
    const int warp_m = w >> 1;       // 0..3 (32 rows each)
    const int warp_n = w & 1;        // 0..1 (64 cols each)
    const int g = lane >> 2;         // fragment group
    const int t = lane & 3;

    float C[2][8][4];
    #pragma unroll
    for (int a = 0; a < 2; a++)
        #pragma unroll
        for (int b = 0; b < 8; b++)
            #pragma unroll
            for (int q = 0; q < 4; q++) C[a][b][q] = 0.0f;

    for (int ch = 0; ch < NCHUNK; ch++) {
        __syncthreads();   // previous chunk's frag reads done

        // ---- load weight tile (hi/lo), [n][k] -> padded smem ----
        {
            const __nv_bfloat16* sh = WBH + ch * (DD * DD);
            const __nv_bfloat16* sl = WBL + ch * (DD * DD);
            #pragma unroll
            for (int v = 0; v < 16; v++) {
                int flat = v * 256 + tid;        // 4096 chunks of 4 bf16
                int n  = flat >> 5;
                int kc = (flat & 31) << 2;
                *(uint2*)(Bs_hi + n * APAD + kc) = *(const uint2*)(sh + n * DD + kc);
                *(uint2*)(Bs_lo + n * APAD + kc) = *(const uint2*)(sl + n * DD + kc);
            }
        }

        // ---- build A tile: per-(node,rel) mean, or raw X for root chunk ----
        if (ch < 8) {
            int i16    = lane & 15;
            int node_l = m0 + w + 8 * i16;
            int segv = 0;
            float cf = 0.f;
            if (node_l < N) {
                int seg = node_l * DR + ch;
                segv = (lane < 16) ? g_rowptr2[seg] : g_rowptr2[seg + 1];
                if (lane < 16) cf = g_coef[seg];
            }
            for (int i = 0; i < 16; i++) {
                int beg  = __shfl_sync(FULLM, segv, i);
                int end  = __shfl_sync(FULLM, segv, i + 16);
                float cc = __shfl_sync(FULLM, cf, i);
                float4 acc = make_float4(0.f, 0.f, 0.f, 0.f);
                for (int e = beg; e < end; e += 32) {
                    int idx = e + lane;
                    int si = (idx < end) ? g_esrc[idx] : 0;
                    int m = end - e; if (m > 32) m = 32;
                    for (int j = 0; j < m; j += 4) {
                        int s0 = __shfl_sync(FULLM, si, j);
                        int s1 = __shfl_sync(FULLM, si, j + 1);
                        int s2 = __shfl_sync(FULLM, si, j + 2);
                        int s3 = __shfl_sync(FULLM, si, j + 3);
                        float4 v0 = *(const float4*)(X + (size_t)s0 * DD + lane * 4);
                        float4 v1 = make_float4(0.f,0.f,0.f,0.f);
                        float4 v2 = make_float4(0.f,0.f,0.f,0.f);
                        float4 v3 = make_float4(0.f,0.f,0.f,0.f);
                        if (j + 1 < m) v1 = *(const float4*)(X + (size_t)s1 * DD + lane * 4);
                        if (j + 2 < m) v2 = *(const float4*)(X + (size_t)s2 * DD + lane * 4);
                        if (j + 3 < m) v3 = *(const float4*)(X + (size_t)s3 * DD + lane * 4);
                        acc.x += v0.x + v1.x + v2.x + v3.x;
                        acc.y += v0.y + v1.y + v2.y + v3.y;
                        acc.z += v0.z + v1.z + v2.z + v3.z;
                        acc.w += v0.w + v1.w + v2.w + v3.w;
                    }
                }
                acc.x *= cc; acc.y *= cc; acc.z *= cc; acc.w *= cc;
                int row = w + 8 * i;
                __nv_bfloat16* dh = As_hi + row * APAD + lane * 4;
                __nv_bfloat16* dl = As_lo + row * APAD + lane * 4;
                float vv[4] = {acc.x, acc.y, acc.z, acc.w};
                #pragma unroll
                for (int q = 0; q < 4; q++) {
                    __nv_bfloat16 hi = __float2bfloat16(vv[q]);
                    dh[q] = hi;
                    dl[q] = __float2bfloat16(vv[q] - __bfloat162float(hi));
                }
            }
        } else {
            // root chunk: A = X tile
            for (int i = 0; i < 16; i++) {
                int row  = w + 8 * i;
                int node = m0 + row;
                float4 v = make_float4(0.f,0.f,0.f,0.f);
                if (node < N) v = *(const float4*)(X + (size_t)node * DD + lane * 4);
                __nv_bfloat16* dh = As_hi + row * APAD + lane * 4;
                __nv_bfloat16* dl = As_lo + row * APAD + lane * 4;
                float vv[4] = {v.x, v.y, v.z, v.w};
                #pragma unroll
                for (int q = 0; q < 4; q++) {
                    __nv_bfloat16 hi = __float2bfloat16(vv[q]);
                    dh[q] = hi;
                    dl[q] = __float2bfloat16(vv[q] - __bfloat162float(hi));
                }
            }
        }
        __syncthreads();

        // ---- MMA: 8 k-steps of m16n8k16, 3-pass split bf16 ----
        #pragma unroll
        for (int ks = 0; ks < 8; ks++) {
            int k0 = ks * 16;
            uint32_t bh[8][2], bl[8][2];
            #pragma unroll
            for (int nf = 0; nf < 8; nf++) {
                int n = warp_n * 64 + nf * 8 + g;
                const __nv_bfloat16* bp = Bs_hi + n * APAD + k0 + 2 * t;
                bh[nf][0] = *(const uint32_t*)bp;
                bh[nf][1] = *(const uint32_t*)(bp + 8);
                const __nv_bfloat16* bq = Bs_lo + n * APAD + k0 + 2 * t;
                bl[nf][0] = *(const uint32_t*)bq;
                bl[nf][1] = *(const uint32_t*)(bq + 8);
            }
            uint32_t ah[2][4], al[2][4];
            #pragma unroll
            for (int mf = 0; mf < 2; mf++) {
                int r0 = warp_m * 32 + mf * 16 + g;
                const __nv_bfloat16* ap = As_hi + r0 * APAD + k0 + 2 * t;
                ah[mf][0] = *(const uint32_t*)ap;
                ah[mf][1] = *(const uint32_t*)(ap + 8 * APAD);
                ah[mf][2] = *(const uint32_t*)(ap + 8);
                ah[mf][3] = *(const uint32_t*)(ap + 8 * APAD + 8);
                const __nv_bfloat16* aq = As_lo + r0 * APAD + k0 + 2 * t;
                al[mf][0] = *(const uint32_t*)aq;
                al[mf][1] = *(const uint32_t*)(aq + 8 * APAD);
                al[mf][2] = *(const uint32_t*)(aq + 8);
                al[mf][3] = *(const uint32_t*)(aq + 8 * APAD + 8);
            }
            #pragma unroll
            for (int mf = 0; mf < 2; mf++)
                #pragma unroll
                for (int nf = 0; nf < 8; nf++) {
                    mma_bf16(C[mf][nf], ah[mf][0], ah[mf][1], ah[mf][2], ah[mf][3],
                             bh[nf][0], bh[nf][1]);
                    mma_bf16(C[mf][nf], ah[mf][0], ah[mf][1], ah[mf][2], ah[mf][3],
                             bl[nf][0], bl[nf][1]);
                    mma_bf16(C[mf][nf], al[mf][0], al[mf][1], al[mf][2], al[mf][3],
                             bh[nf][0], bh[nf][1]);
                }
        }
    }

    // ---- epilogue: + bias, ReLU ----
    #pragma unroll
    for (int mf = 0; mf < 2; mf++)
        #pragma unroll
        for (int nf = 0; nf < 8; nf++) {
            int row = warp_m * 32 + mf * 16 + g;
            int col = warp_n * 64 + nf * 8 + 2 * t;
            float b0 = bias[col], b1 = bias[col + 1];
            int node0 = m0 + row;
            if (node0 < N) {
                float o0 = C[mf][nf][0] + b0; o0 = o0 > 0.f ? o0 : 0.f;
                float o1 = C[mf][nf][1] + b1; o1 = o1 > 0.f ? o1 : 0.f;
                float2* p = (float2*)(out + (size_t)node0 * DD + col);
                *p = make_float2(o0, o1);
            }
            int node1 = m0 + row + 8;
            if (node1 < N) {
                float o2 = C[mf][nf][2] + b0; o2 = o2 > 0.f ? o2 : 0.f;
                float o3 = C[mf][nf][3] + b1; o3 = o3 > 0.f ? o3 : 0.f;
                float2* p = (float2*)(out + (size_t)node1 * DD + col);
                *p = make_float2(o2, o3);
            }
        }
}

// ---------------- launch ----------------
extern "C" void kernel_launch(void* const* d_in, const int* in_sizes, int n_in,
                              void* d_out, int out_size) {
    const float* x     = (const float*)d_in[0];
    const int*   ei    = (const int*)d_in[1];
    const int*   et    = (const int*)d_in[2];
    const float* W1    = (const float*)d_in[3];
    const float* root1 = (const float*)d_in[4];
    const float* b1    = (const float*)d_in[5];
    const float* W2    = (const float*)d_in[6];
    const float* root2 = (const float*)d_in[7];
    const float* b2    = (const float*)d_in[8];
    const float* rel   = (const float*)d_in[9];

    const int N = in_sizes[0] / DD;   // 50000
    const int E = in_sizes[2];        // 600000

    float* h1;  cudaGetSymbolAddress((void**)&h1, g_h);
    __nv_bfloat16* wbh; cudaGetSymbolAddress((void**)&wbh, g_wbh);
    __nv_bfloat16* wbl; cudaGetSymbolAddress((void**)&wbl, g_wbl);

    float* out_h   = (float*)d_out;
    float* out_rel = (float*)d_out + (size_t)N * DD;

    static int smem_set = 0;
    if (!smem_set) {
        cudaFuncSetAttribute(fused_layer_kernel,
                             cudaFuncAttributeMaxDynamicSharedMemorySize, SMEM_BYTES);
        smem_set = 1;
    }

    // ---- preprocessing ----
    zero_cnt_kernel<<<(NR + 255) / 256, 256>>>();
    count_kernel<<<(E + 255) / 256, 256>>>(ei, et, E);
    const int nb = (NR + 1023) / 1024;   // 391
    scanA_kernel<<<nb, 1024>>>();
    scanB_kernel<<<1, 512>>>(nb);
    scanC_kernel<<<(NR + 255) / 256, 256>>>(E);
    scatter_kernel<<<(E + 255) / 256, 256>>>(ei, et, E);
    wprep_kernel<<<(2 * NCHUNK * DD * DD + 255) / 256, 256>>>(W1, root1, W2, root2);

    const int grid = (N + 127) / 128;    // 391

    // ---- layer 1 ----
    fused_layer_kernel<<<grid, 256, SMEM_BYTES>>>(x, wbh, wbl, b1, h1, N);
    // ---- layer 2 ----
    fused_layer_kernel<<<grid, 256, SMEM_BYTES>>>(
        h1, wbh + NCHUNK * DD * DD, wbl + NCHUNK * DD * DD, b2, out_h, N);

    // ---- append rel_emb ----
    copy_rel_kernel<<<1, 1024>>>(rel, out_rel, DR * DD);
}

// round 6
// speedup vs baseline: 1.7461x; 1.1456x over previous
#include <cuda_runtime.h>
#include <cuda_bf16.h>
#include <stdint.h>

// Problem constants (fixed by dataset)
#define DN 50000     // nodes
#define DE 600000    // edges
#define DD 128       // feature dim
#define DR 8         // relations
#define NR (DR * DN) // 400000 (rel,dst) segments, rel-major
#define NCHUNK 9     // 8 relations + root
#define FULLM 0xffffffffu

// ---------------- scratch (device globals; no allocs allowed) ----------------
__device__ int   g_cnt[NR];              // per-(rel,dst) edge counts
__device__ int   g_rowptr2[NR + 1];      // CSR row pointers, rel-major
__device__ int   g_woff[NR];             // working offsets for scatter
__device__ int   g_bsum[512];            // scan block sums
__device__ int   g_boff[512];            // scan block offsets
__device__ int2  g_emeta[DE];            // per-edge: .x = src | (dst<<16), .y = coef bits
__device__ float g_h[(size_t)DN * DD];   // layer-1 output
// weight tiles, bf16 hi/lo, transposed layout [layer][chunk][n][k]
__device__ __nv_bfloat16 g_wbh[2 * NCHUNK * DD * DD];
__device__ __nv_bfloat16 g_wbl[2 * NCHUNK * DD * DD];

// ---------------- preprocessing kernels ----------------
__global__ void zero_cnt_kernel() {
    int i = blockIdx.x * blockDim.x + threadIdx.x;
    if (i < NR) g_cnt[i] = 0;
}

__global__ void count_kernel(const int* __restrict__ ei, const int* __restrict__ et, int E) {
    int e = blockIdx.x * blockDim.x + threadIdx.x;
    if (e < E) {
        int d = ei[E + e];
        int t = et[e];
        atomicAdd(&g_cnt[t * DN + d], 1);   // rel-major
    }
}

__global__ void scanA_kernel() {
    __shared__ int s[1024];
    int tid = threadIdx.x;
    int i = blockIdx.x * 1024 + tid;
    int v = (i < NR) ? g_cnt[i] : 0;
    s[tid] = v;
    __syncthreads();
    for (int off = 1; off < 1024; off <<= 1) {
        int t = (tid >= off) ? s[tid - off] : 0;
        __syncthreads();
        s[tid] += t;
        __syncthreads();
    }
    if (i < NR) g_rowptr2[i] = s[tid] - v;   // block-local exclusive
    if (tid == 1023) g_bsum[blockIdx.x] = s[1023];
}

__global__ void scanB_kernel(int nb) {
    __shared__ int s[512];
    int tid = threadIdx.x;
    int v = (tid < nb) ? g_bsum[tid] : 0;
    s[tid] = v;
    __syncthreads();
    for (int off = 1; off < 512; off <<= 1) {
        int t = (tid >= off) ? s[tid - off] : 0;
        __syncthreads();
        s[tid] += t;
        __syncthreads();
    }
    g_boff[tid] = s[tid] - v;   // exclusive
}

__global__ void scanC_kernel(int E) {
    int i = blockIdx.x * blockDim.x + threadIdx.x;
    if (i < NR) {
        int st = g_rowptr2[i] + g_boff[i >> 10];
        g_rowptr2[i] = st;
        g_woff[i] = st;
        if (i == 0) g_rowptr2[NR] = E;
    }
}

__global__ void scatter_kernel(const int* __restrict__ ei, const int* __restrict__ et, int E) {
    int e = blockIdx.x * blockDim.x + threadIdx.x;
    if (e < E) {
        int s = ei[e];
        int d = ei[E + e];
        int t = et[e];
        int seg = t * DN + d;
        int pos = atomicAdd(&g_woff[seg], 1);
        int c = g_cnt[seg];
        float coef = 1.0f / (float)(c > 0 ? c : 1);
        g_emeta[pos] = make_int2((int)((unsigned)s | ((unsigned)d << 16)),
                                 __float_as_int(coef));
    }
}

// convert + transpose weights into bf16 hi/lo tiles: g_wb[l][ch][n][k]
__global__ void wprep_kernel(const float* __restrict__ W1, const float* __restrict__ r1,
                             const float* __restrict__ W2, const float* __restrict__ r2) {
    int id = blockIdx.x * blockDim.x + threadIdx.x;
    const int total = 2 * NCHUNK * DD * DD;
    if (id >= total) return;
    int l   = id / (NCHUNK * DD * DD);
    int rem = id % (NCHUNK * DD * DD);
    int ch  = rem / (DD * DD);
    int pos = rem % (DD * DD);
    int n = pos >> 7, k = pos & 127;
    const float* W  = l ? W2 : W1;
    const float* rt = l ? r2 : r1;
    float wv = (ch < 8) ? W[((size_t)ch * DD + k) * DD + n] : rt[(size_t)k * DD + n];
    __nv_bfloat16 hi = __float2bfloat16(wv);
    float lo = wv - __bfloat162float(hi);
    g_wbh[id] = hi;
    g_wbl[id] = __float2bfloat16(lo);
}

__global__ void copy_rel_kernel(const float* __restrict__ rel, float* __restrict__ out, int n) {
    int i = blockIdx.x * blockDim.x + threadIdx.x;
    if (i < n) out[i] = rel[i];
}

// ---------------- fused RGCN layer ----------------
__device__ __forceinline__ void mma_bf16(float c[4],
    uint32_t a0, uint32_t a1, uint32_t a2, uint32_t a3,
    uint32_t b0, uint32_t b1)
{
    asm volatile(
        "mma.sync.aligned.m16n8k16.row.col.f32.bf16.bf16.f32 "
        "{%0,%1,%2,%3}, {%4,%5,%6,%7}, {%8,%9}, {%0,%1,%2,%3};\n"
        : "+f"(c[0]), "+f"(c[1]), "+f"(c[2]), "+f"(c[3])
        : "r"(a0), "r"(a1), "r"(a2), "r"(a3), "r"(b0), "r"(b1));
}

#define APAD  136  // bf16 row stride (conflict-free frag loads)
#define APADF 132  // fp32 accumulation tile row stride
#define SMEM_BYTES (128 * APADF * 4 + 4 * 128 * APAD * 2)

__global__ __launch_bounds__(256, 1) void fused_layer_kernel(
    const float* __restrict__ X,
    const __nv_bfloat16* __restrict__ WBH,
    const __nv_bfloat16* __restrict__ WBL,
    const float* __restrict__ bias,
    float* __restrict__ out, int N)
{
    extern __shared__ char smem[];
    float*         As_f  = (float*)smem;                       // 128 x APADF fp32
    __nv_bfloat16* As_hi = (__nv_bfloat16*)(As_f + 128 * APADF);
    __nv_bfloat16* As_lo = As_hi + 128 * APAD;
    __nv_bfloat16* Bs_hi = As_lo + 128 * APAD;
    __nv_bfloat16* Bs_lo = Bs_hi + 128 * APAD;

    const int tid  = threadIdx.x;
    const int w    = tid >> 5;
    const int lane = tid & 31;
    const int m0   = blockIdx.x * 128;
    const int warp_m = w >> 1;
    const int warp_n = w & 1;
    const int g = lane >> 2;
    const int t = lane & 3;

    float C[2][8][4];
    #pragma unroll
    for (int a = 0; a < 2; a++)
        #pragma unroll
        for (int b = 0; b < 8; b++)
            #pragma unroll
            for (int q = 0; q < 4; q++) C[a][b][q] = 0.0f;

    for (int ch = 0; ch < NCHUNK; ch++) {
        __syncthreads();   // previous chunk's frag reads done

        // ---- load weight tile (hi/lo), [n][k] -> padded smem ----
        {
            const __nv_bfloat16* sh = WBH + ch * (DD * DD);
            const __nv_bfloat16* sl = WBL + ch * (DD * DD);
            #pragma unroll
            for (int v = 0; v < 16; v++) {
                int flat = v * 256 + tid;
                int n  = flat >> 5;
                int kc = (flat & 31) << 2;
                *(uint2*)(Bs_hi + n * APAD + kc) = *(const uint2*)(sh + n * DD + kc);
                *(uint2*)(Bs_lo + n * APAD + kc) = *(const uint2*)(sl + n * DD + kc);
            }
        }

        // ---- build A tile ----
        if (ch < 8) {
            const int w16 = w * 16;   // this warp's 16 contiguous rows
            // zero fp32 tile rows (exclusive ownership)
            #pragma unroll
            for (int i = 0; i < 16; i++)
                *(float4*)(As_f + (w16 + i) * APADF + lane * 4) =
                    make_float4(0.f, 0.f, 0.f, 0.f);

            int r0c = m0 + w16;     if (r0c > N) r0c = N;
            int r1c = m0 + w16 + 16; if (r1c > N) r1c = N;
            int wbeg = g_rowptr2[ch * DN + r0c];
            int wend = g_rowptr2[ch * DN + r1c];

            for (int e0 = wbeg; e0 < wend; e0 += 32) {
                int idx = e0 + lane;
                int2 mt = make_int2(0, 0);
                if (idx < wend) mt = g_emeta[idx];
                int cnt = wend - e0; if (cnt > 32) cnt = 32;
                for (int j = 0; j < cnt; j += 4) {
                    int nb = cnt - j; if (nb > 4) nb = 4;
                    int pk[4]; float cc[4]; float4 v[4];
                    #pragma unroll
                    for (int q = 0; q < 4; q++) {
                        pk[q] = __shfl_sync(FULLM, mt.x, j + q);
                        cc[q] = __shfl_sync(FULLM, __int_as_float(mt.y), j + q);
                    }
                    #pragma unroll
                    for (int q = 0; q < 4; q++)
                        if (q < nb)
                            v[q] = *(const float4*)(X +
                                   (size_t)((unsigned)pk[q] & 0xffffu) * DD + lane * 4);
                    #pragma unroll
                    for (int q = 0; q < 4; q++)
                        if (q < nb) {
                            int dl = (int)(((unsigned)pk[q]) >> 16) - m0;
                            float* rp = As_f + dl * APADF + lane * 4;
                            float4 cur = *(float4*)rp;
                            cur.x += cc[q] * v[q].x;
                            cur.y += cc[q] * v[q].y;
                            cur.z += cc[q] * v[q].z;
                            cur.w += cc[q] * v[q].w;
                            *(float4*)rp = cur;
                        }
                }
            }
            // convert this warp's rows fp32 -> bf16 hi/lo
            #pragma unroll
            for (int i = 0; i < 16; i++) {
                int row = w16 + i;
                float4 vv4 = *(float4*)(As_f + row * APADF + lane * 4);
                float vv[4] = {vv4.x, vv4.y, vv4.z, vv4.w};
                __nv_bfloat16* dh = As_hi + row * APAD + lane * 4;
                __nv_bfloat16* dl = As_lo + row * APAD + lane * 4;
                #pragma unroll
                for (int q = 0; q < 4; q++) {
                    __nv_bfloat16 hi = __float2bfloat16(vv[q]);
                    dh[q] = hi;
                    dl[q] = __float2bfloat16(vv[q] - __bfloat162float(hi));
                }
            }
        } else {
            // root chunk: A = X tile
            #pragma unroll
            for (int i = 0; i < 16; i++) {
                int row  = w * 16 + i;
                int node = m0 + row;
                float4 v = make_float4(0.f, 0.f, 0.f, 0.f);
                if (node < N) v = *(const float4*)(X + (size_t)node * DD + lane * 4);
                __nv_bfloat16* dh = As_hi + row * APAD + lane * 4;
                __nv_bfloat16* dl = As_lo + row * APAD + lane * 4;
                float vv[4] = {v.x, v.y, v.z, v.w};
                #pragma unroll
                for (int q = 0; q < 4; q++) {
                    __nv_bfloat16 hi = __float2bfloat16(vv[q]);
                    dh[q] = hi;
                    dl[q] = __float2bfloat16(vv[q] - __bfloat162float(hi));
                }
            }
        }
        __syncthreads();

        // ---- MMA: 8 k-steps of m16n8k16, 3-pass split bf16 ----
        #pragma unroll
        for (int ks = 0; ks < 8; ks++) {
            int k0 = ks * 16;
            uint32_t bh[8][2], bl[8][2];
            #pragma unroll
            for (int nf = 0; nf < 8; nf++) {
                int n = warp_n * 64 + nf * 8 + g;
                const __nv_bfloat16* bp = Bs_hi + n * APAD + k0 + 2 * t;
                bh[nf][0] = *(const uint32_t*)bp;
                bh[nf][1] = *(const uint32_t*)(bp + 8);
                const __nv_bfloat16* bq = Bs_lo + n * APAD + k0 + 2 * t;
                bl[nf][0] = *(const uint32_t*)bq;
                bl[nf][1] = *(const uint32_t*)(bq + 8);
            }
            uint32_t ah[2][4], al[2][4];
            #pragma unroll
            for (int mf = 0; mf < 2; mf++) {
                int r0 = warp_m * 32 + mf * 16 + g;
                const __nv_bfloat16* ap = As_hi + r0 * APAD + k0 + 2 * t;
                ah[mf][0] = *(const uint32_t*)ap;
                ah[mf][1] = *(const uint32_t*)(ap + 8 * APAD);
                ah[mf][2] = *(const uint32_t*)(ap + 8);
                ah[mf][3] = *(const uint32_t*)(ap + 8 * APAD + 8);
                const __nv_bfloat16* aq = As_lo + r0 * APAD + k0 + 2 * t;
                al[mf][0] = *(const uint32_t*)aq;
                al[mf][1] = *(const uint32_t*)(aq + 8 * APAD);
                al[mf][2] = *(const uint32_t*)(aq + 8);
                al[mf][3] = *(const uint32_t*)(aq + 8 * APAD + 8);
            }
            #pragma unroll
            for (int mf = 0; mf < 2; mf++)
                #pragma unroll
                for (int nf = 0; nf < 8; nf++) {
                    mma_bf16(C[mf][nf], ah[mf][0], ah[mf][1], ah[mf][2], ah[mf][3],
                             bh[nf][0], bh[nf][1]);
                    mma_bf16(C[mf][nf], ah[mf][0], ah[mf][1], ah[mf][2], ah[mf][3],
                             bl[nf][0], bl[nf][1]);
                    mma_bf16(C[mf][nf], al[mf][0], al[mf][1], al[mf][2], al[mf][3],
                             bh[nf][0], bh[nf][1]);
                }
        }
    }

    // ---- epilogue: + bias, ReLU ----
    #pragma unroll
    for (int mf = 0; mf < 2; mf++)
        #pragma unroll
        for (int nf = 0; nf < 8; nf++) {
            int row = warp_m * 32 + mf * 16 + g;
            int col = warp_n * 64 + nf * 8 + 2 * t;
            float b0 = bias[col], b1 = bias[col + 1];
            int node0 = m0 + row;
            if (node0 < N) {
                float o0 = C[mf][nf][0] + b0; o0 = o0 > 0.f ? o0 : 0.f;
                float o1 = C[mf][nf][1] + b1; o1 = o1 > 0.f ? o1 : 0.f;
                *(float2*)(out + (size_t)node0 * DD + col) = make_float2(o0, o1);
            }
            int node1 = m0 + row + 8;
            if (node1 < N) {
                float o2 = C[mf][nf][2] + b0; o2 = o2 > 0.f ? o2 : 0.f;
                float o3 = C[mf][nf][3] + b1; o3 = o3 > 0.f ? o3 : 0.f;
                *(float2*)(out + (size_t)node1 * DD + col) = make_float2(o2, o3);
            }
        }
}

// ---------------- launch ----------------
extern "C" void kernel_launch(void* const* d_in, const int* in_sizes, int n_in,
                              void* d_out, int out_size) {
    const float* x     = (const float*)d_in[0];
    const int*   ei    = (const int*)d_in[1];
    const int*   et    = (const int*)d_in[2];
    const float* W1    = (const float*)d_in[3];
    const float* root1 = (const float*)d_in[4];
    const float* b1    = (const float*)d_in[5];
    const float* W2    = (const float*)d_in[6];
    const float* root2 = (const float*)d_in[7];
    const float* b2    = (const float*)d_in[8];
    const float* rel   = (const float*)d_in[9];

    const int N = in_sizes[0] / DD;   // 50000
    const int E = in_sizes[2];        // 600000

    float* h1;  cudaGetSymbolAddress((void**)&h1, g_h);
    __nv_bfloat16* wbh; cudaGetSymbolAddress((void**)&wbh, g_wbh);
    __nv_bfloat16* wbl; cudaGetSymbolAddress((void**)&wbl, g_wbl);

    float* out_h   = (float*)d_out;
    float* out_rel = (float*)d_out + (size_t)N * DD;

    static int smem_set = 0;
    if (!smem_set) {
        cudaFuncSetAttribute(fused_layer_kernel,
                             cudaFuncAttributeMaxDynamicSharedMemorySize, SMEM_BYTES);
        smem_set = 1;
    }

    // ---- preprocessing ----
    zero_cnt_kernel<<<(NR + 255) / 256, 256>>>();
    count_kernel<<<(E + 255) / 256, 256>>>(ei, et, E);
    const int nb = (NR + 1023) / 1024;   // 391
    scanA_kernel<<<nb, 1024>>>();
    scanB_kernel<<<1, 512>>>(nb);
    scanC_kernel<<<(NR + 255) / 256, 256>>>(E);
    scatter_kernel<<<(E + 255) / 256, 256>>>(ei, et, E);
    wprep_kernel<<<(2 * NCHUNK * DD * DD + 255) / 256, 256>>>(W1, root1, W2, root2);

    const int grid = (N + 127) / 128;    // 391

    // ---- layer 1 ----
    fused_layer_kernel<<<grid, 256, SMEM_BYTES>>>(x, wbh, wbl, b1, h1, N);
    // ---- layer 2 ----
    fused_layer_kernel<<<grid, 256, SMEM_BYTES>>>(
        h1, wbh + NCHUNK * DD * DD, wbl + NCHUNK * DD * DD, b2, out_h, N);

    // ---- append rel_emb ----
    copy_rel_kernel<<<1, 1024>>>(rel, out_rel, DR * DD);
}

// round 7
// speedup vs baseline: 2.2021x; 1.2612x over previous
#include <cuda_runtime.h>
#include <cuda_bf16.h>
#include <stdint.h>

// Problem constants (fixed by dataset)
#define DN 50000     // nodes
#define DE 600000    // edges
#define DD 128       // feature dim
#define DR 8         // relations
#define NR (DR * DN) // 400000 (rel,dst) segments, rel-major
#define NCHUNK 9     // 8 relations + root
#define FULLM 0xffffffffu

// ---------------- scratch (device globals; no allocs allowed) ----------------
__device__ int   g_cnt[NR];              // per-(rel,dst) edge counts
__device__ int   g_rowptr2[NR + 1];      // CSR row pointers, rel-major
__device__ int   g_woff[NR];             // working offsets for scatter
__device__ int   g_bsum[512];            // scan block sums
__device__ int   g_boff[512];            // scan block offsets
__device__ int2  g_emeta[DE];            // per-edge: .x = src | (dst<<16), .y = coef bits
__device__ float g_h[(size_t)DN * DD];   // layer-1 output
// weight tiles, tf32-rounded fp32, transposed layout [layer][chunk][n][k]
__device__ float g_wt[2 * NCHUNK * DD * DD];

__device__ __forceinline__ float to_tf32(float x) {
    float r;
    asm("cvt.rna.tf32.f32 %0, %1;" : "=f"(r) : "f"(x));
    return r;
}

// ---------------- preprocessing kernels ----------------
__global__ void zero_cnt_kernel() {
    int i = blockIdx.x * blockDim.x + threadIdx.x;
    if (i < NR) g_cnt[i] = 0;
}

__global__ void count_kernel(const int* __restrict__ ei, const int* __restrict__ et, int E) {
    int e = blockIdx.x * blockDim.x + threadIdx.x;
    if (e < E) {
        int d = ei[E + e];
        int t = et[e];
        atomicAdd(&g_cnt[t * DN + d], 1);   // rel-major
    }
}

__global__ void scanA_kernel() {
    __shared__ int s[1024];
    int tid = threadIdx.x;
    int i = blockIdx.x * 1024 + tid;
    int v = (i < NR) ? g_cnt[i] : 0;
    s[tid] = v;
    __syncthreads();
    for (int off = 1; off < 1024; off <<= 1) {
        int t = (tid >= off) ? s[tid - off] : 0;
        __syncthreads();
        s[tid] += t;
        __syncthreads();
    }
    if (i < NR) g_rowptr2[i] = s[tid] - v;   // block-local exclusive
    if (tid == 1023) g_bsum[blockIdx.x] = s[1023];
}

__global__ void scanB_kernel(int nb) {
    __shared__ int s[512];
    int tid = threadIdx.x;
    int v = (tid < nb) ? g_bsum[tid] : 0;
    s[tid] = v;
    __syncthreads();
    for (int off = 1; off < 512; off <<= 1) {
        int t = (tid >= off) ? s[tid - off] : 0;
        __syncthreads();
        s[tid] += t;
        __syncthreads();
    }
    g_boff[tid] = s[tid] - v;   // exclusive
}

__global__ void scanC_kernel(int E) {
    int i = blockIdx.x * blockDim.x + threadIdx.x;
    if (i < NR) {
        int st = g_rowptr2[i] + g_boff[i >> 10];
        g_rowptr2[i] = st;
        g_woff[i] = st;
        if (i == 0) g_rowptr2[NR] = E;
    }
}

__global__ void scatter_kernel(const int* __restrict__ ei, const int* __restrict__ et, int E) {
    int e = blockIdx.x * blockDim.x + threadIdx.x;
    if (e < E) {
        int s = ei[e];
        int d = ei[E + e];
        int t = et[e];
        int seg = t * DN + d;
        int pos = atomicAdd(&g_woff[seg], 1);
        int c = g_cnt[seg];
        float coef = 1.0f / (float)(c > 0 ? c : 1);
        g_emeta[pos] = make_int2((int)((unsigned)s | ((unsigned)d << 16)),
                                 __float_as_int(coef));
    }
}

// convert + transpose weights to tf32-rounded fp32: g_wt[l][ch][n][k]
__global__ void wprep_kernel(const float* __restrict__ W1, const float* __restrict__ r1,
                             const float* __restrict__ W2, const float* __restrict__ r2) {
    int id = blockIdx.x * blockDim.x + threadIdx.x;
    const int total = 2 * NCHUNK * DD * DD;
    if (id >= total) return;
    int l   = id / (NCHUNK * DD * DD);
    int rem = id % (NCHUNK * DD * DD);
    int ch  = rem / (DD * DD);
    int pos = rem % (DD * DD);
    int n = pos >> 7, k = pos & 127;
    const float* W  = l ? W2 : W1;
    const float* rt = l ? r2 : r1;
    float wv = (ch < 8) ? W[((size_t)ch * DD + k) * DD + n] : rt[(size_t)k * DD + n];
    g_wt[id] = to_tf32(wv);
}

__global__ void copy_rel_kernel(const float* __restrict__ rel, float* __restrict__ out, int n) {
    int i = blockIdx.x * blockDim.x + threadIdx.x;
    if (i < n) out[i] = rel[i];
}

// ---------------- fused RGCN layer (tf32 mma, M-tile=64, 2 CTA/SM) ----------------
__device__ __forceinline__ void mma_tf32(float c[4],
    uint32_t a0, uint32_t a1, uint32_t a2, uint32_t a3,
    uint32_t b0, uint32_t b1)
{
    asm volatile(
        "mma.sync.aligned.m16n8k8.row.col.f32.tf32.tf32.f32 "
        "{%0,%1,%2,%3}, {%4,%5,%6,%7}, {%8,%9}, {%0,%1,%2,%3};\n"
        : "+f"(c[0]), "+f"(c[1]), "+f"(c[2]), "+f"(c[3])
        : "r"(a0), "r"(a1), "r"(a2), "r"(a3), "r"(b0), "r"(b1));
}

#define MT    64   // M tile (nodes per CTA)
#define PAD   132  // fp32 row stride (conflict-free frag loads)
#define SMEM_BYTES ((MT * PAD + 128 * PAD) * 4)   // A tile + B tile

__global__ __launch_bounds__(128, 2) void fused_layer_kernel(
    const float* __restrict__ X,
    const float* __restrict__ WT,    // layer base of g_wt
    const float* __restrict__ bias,
    float* __restrict__ out, int N)
{
    extern __shared__ char smem[];
    float* As = (float*)smem;            // MT x PAD fp32 (tf32-rounded)
    float* Bs = As + MT * PAD;           // 128 x PAD fp32 (tf32-rounded)

    const int tid  = threadIdx.x;
    const int w    = tid >> 5;           // 0..3
    const int lane = tid & 31;
    const int m0   = blockIdx.x * MT;
    const int warp_m = w >> 1;           // 0..1 (32 rows)
    const int warp_n = w & 1;            // 0..1 (64 cols)
    const int g = lane >> 2;             // 0..7
    const int t = lane & 3;              // 0..3

    float C[2][8][4];
    #pragma unroll
    for (int a = 0; a < 2; a++)
        #pragma unroll
        for (int b = 0; b < 8; b++)
            #pragma unroll
            for (int q = 0; q < 4; q++) C[a][b][q] = 0.0f;

    const int w16 = w * 16;              // this warp's 16 contiguous A rows

    for (int ch = 0; ch < NCHUNK; ch++) {
        __syncthreads();   // previous chunk's frag reads done; smem reusable

        // ---- B tile via cp.async (overlaps with gather below) ----
        {
            const float* src = WT + ch * (DD * DD);
            #pragma unroll
            for (int v = 0; v < 32; v++) {
                int flat = v * 128 + tid;          // 4096 chunks of 4 floats
                int n  = flat >> 5;
                int kc = (flat & 31) << 2;
                uint32_t daddr = (uint32_t)__cvta_generic_to_shared(Bs + n * PAD + kc);
                asm volatile("cp.async.cg.shared.global [%0], [%1], 16;\n"
                             :: "r"(daddr), "l"(src + n * DD + kc));
            }
            asm volatile("cp.async.commit_group;\n");
        }

        // ---- build A tile (fp32) ----
        if (ch < 8) {
            // zero this warp's rows (exclusive ownership)
            #pragma unroll
            for (int i = 0; i < 16; i++)
                *(float4*)(As + (w16 + i) * PAD + lane * 4) =
                    make_float4(0.f, 0.f, 0.f, 0.f);

            int r0c = m0 + w16;      if (r0c > N) r0c = N;
            int r1c = m0 + w16 + 16; if (r1c > N) r1c = N;
            int wbeg = g_rowptr2[ch * DN + r0c];
            int wend = g_rowptr2[ch * DN + r1c];

            for (int e0 = wbeg; e0 < wend; e0 += 32) {
                int idx = e0 + lane;
                int2 mt = make_int2(0, 0);
                if (idx < wend) mt = g_emeta[idx];
                int cnt = wend - e0; if (cnt > 32) cnt = 32;
                for (int j = 0; j < cnt; j += 4) {
                    int nb = cnt - j; if (nb > 4) nb = 4;
                    int pk[4]; float cc[4]; float4 v[4];
                    #pragma unroll
                    for (int q = 0; q < 4; q++) {
                        pk[q] = __shfl_sync(FULLM, mt.x, j + q);
                        cc[q] = __shfl_sync(FULLM, __int_as_float(mt.y), j + q);
                    }
                    #pragma unroll
                    for (int q = 0; q < 4; q++)
                        if (q < nb)
                            v[q] = *(const float4*)(X +
                                   (size_t)((unsigned)pk[q] & 0xffffu) * DD + lane * 4);
                    #pragma unroll
                    for (int q = 0; q < 4; q++)
                        if (q < nb) {
                            int dl = (int)(((unsigned)pk[q]) >> 16) - m0;
                            float* rp = As + dl * PAD + lane * 4;
                            float4 cur = *(float4*)rp;
                            cur.x += cc[q] * v[q].x;
                            cur.y += cc[q] * v[q].y;
                            cur.z += cc[q] * v[q].z;
                            cur.w += cc[q] * v[q].w;
                            *(float4*)rp = cur;
                        }
                }
            }
            // tf32-round this warp's rows in place
            #pragma unroll
            for (int i = 0; i < 16; i++) {
                float* rp = As + (w16 + i) * PAD + lane * 4;
                float4 vv = *(float4*)rp;
                vv.x = to_tf32(vv.x); vv.y = to_tf32(vv.y);
                vv.z = to_tf32(vv.z); vv.w = to_tf32(vv.w);
                *(float4*)rp = vv;
            }
        } else {
            // root chunk: A = X tile (tf32-rounded)
            #pragma unroll
            for (int i = 0; i < 16; i++) {
                int row  = w16 + i;
                int node = m0 + row;
                float4 v = make_float4(0.f, 0.f, 0.f, 0.f);
                if (node < N) v = *(const float4*)(X + (size_t)node * DD + lane * 4);
                v.x = to_tf32(v.x); v.y = to_tf32(v.y);
                v.z = to_tf32(v.z); v.w = to_tf32(v.w);
                *(float4*)(As + row * PAD + lane * 4) = v;
            }
        }
        asm volatile("cp.async.wait_group 0;\n" ::: "memory");
        __syncthreads();

        // ---- MMA: 16 k-steps of m16n8k8 tf32 ----
        #pragma unroll
        for (int ks = 0; ks < 16; ks++) {
            int k0 = ks * 8;
            uint32_t bf[8][2];
            #pragma unroll
            for (int nf = 0; nf < 8; nf++) {
                int n = warp_n * 64 + nf * 8 + g;
                const float* bp = Bs + n * PAD + k0;
                bf[nf][0] = __float_as_uint(bp[t]);
                bf[nf][1] = __float_as_uint(bp[t + 4]);
            }
            uint32_t af[2][4];
            #pragma unroll
            for (int mf = 0; mf < 2; mf++) {
                int r0 = warp_m * 32 + mf * 16 + g;
                const float* ap = As + r0 * PAD + k0;
                af[mf][0] = __float_as_uint(ap[t]);
                af[mf][1] = __float_as_uint(ap[8 * PAD + t]);
                af[mf][2] = __float_as_uint(ap[t + 4]);
                af[mf][3] = __float_as_uint(ap[8 * PAD + t + 4]);
            }
            #pragma unroll
            for (int mf = 0; mf < 2; mf++)
                #pragma unroll
                for (int nf = 0; nf < 8; nf++)
                    mma_tf32(C[mf][nf], af[mf][0], af[mf][1], af[mf][2], af[mf][3],
                             bf[nf][0], bf[nf][1]);
        }
    }

    // ---- epilogue: + bias, ReLU ----
    #pragma unroll
    for (int mf = 0; mf < 2; mf++)
        #pragma unroll
        for (int nf = 0; nf < 8; nf++) {
            int row = warp_m * 32 + mf * 16 + g;
            int col = warp_n * 64 + nf * 8 + 2 * t;
            float b0 = bias[col], b1 = bias[col + 1];
            int node0 = m0 + row;
            if (node0 < N) {
                float o0 = C[mf][nf][0] + b0; o0 = o0 > 0.f ? o0 : 0.f;
                float o1 = C[mf][nf][1] + b1; o1 = o1 > 0.f ? o1 : 0.f;
                *(float2*)(out + (size_t)node0 * DD + col) = make_float2(o0, o1);
            }
            int node1 = m0 + row + 8;
            if (node1 < N) {
                float o2 = C[mf][nf][2] + b0; o2 = o2 > 0.f ? o2 : 0.f;
                float o3 = C[mf][nf][3] + b1; o3 = o3 > 0.f ? o3 : 0.f;
                *(float2*)(out + (size_t)node1 * DD + col) = make_float2(o2, o3);
            }
        }
}

// ---------------- launch ----------------
extern "C" void kernel_launch(void* const* d_in, const int* in_sizes, int n_in,
                              void* d_out, int out_size) {
    const float* x     = (const float*)d_in[0];
    const int*   ei    = (const int*)d_in[1];
    const int*   et    = (const int*)d_in[2];
    const float* W1    = (const float*)d_in[3];
    const float* root1 = (const float*)d_in[4];
    const float* b1    = (const float*)d_in[5];
    const float* W2    = (const float*)d_in[6];
    const float* root2 = (const float*)d_in[7];
    const float* b2    = (const float*)d_in[8];
    const float* rel   = (const float*)d_in[9];

    const int N = in_sizes[0] / DD;   // 50000
    const int E = in_sizes[2];        // 600000

    float* h1;  cudaGetSymbolAddress((void**)&h1, g_h);
    float* wt;  cudaGetSymbolAddress((void**)&wt, g_wt);

    float* out_h   = (float*)d_out;
    float* out_rel = (float*)d_out + (size_t)N * DD;

    static int smem_set = 0;
    if (!smem_set) {
        cudaFuncSetAttribute(fused_layer_kernel,
                             cudaFuncAttributeMaxDynamicSharedMemorySize, SMEM_BYTES);
        smem_set = 1;
    }

    // ---- preprocessing ----
    zero_cnt_kernel<<<(NR + 255) / 256, 256>>>();
    count_kernel<<<(E + 255) / 256, 256>>>(ei, et, E);
    const int nb = (NR + 1023) / 1024;   // 391
    scanA_kernel<<<nb, 1024>>>();
    scanB_kernel<<<1, 512>>>(nb);
    scanC_kernel<<<(NR + 255) / 256, 256>>>(E);
    scatter_kernel<<<(E + 255) / 256, 256>>>(ei, et, E);
    wprep_kernel<<<(2 * NCHUNK * DD * DD + 255) / 256, 256>>>(W1, root1, W2, root2);

    const int grid = (N + MT - 1) / MT;   // 782

    // ---- layer 1 ----
    fused_layer_kernel<<<grid, 128, SMEM_BYTES>>>(x, wt, b1, h1, N);
    // ---- layer 2 ----
    fused_layer_kernel<<<grid, 128, SMEM_BYTES>>>(h1, wt + NCHUNK * DD * DD, b2, out_h, N);

    // ---- append rel_emb ----
    copy_rel_kernel<<<1, 1024>>>(rel, out_rel, DR * DD);
}

// round 8
// speedup vs baseline: 2.3377x; 1.0616x over previous
#include <cuda_runtime.h>
#include <cuda_bf16.h>
#include <stdint.h>

// Problem constants (fixed by dataset)
#define DN 50000     // nodes
#define DE 600000    // edges
#define DD 128       // feature dim
#define DR 8         // relations
#define NR (DR * DN) // 400000 (rel,dst) segments, rel-major
#define NCHUNK 9     // 8 relations + root
#define FULLM 0xffffffffu

// ---------------- scratch (device globals; no allocs allowed) ----------------
// g_cnt must be zero at entry; module-load zero-init covers the first call,
// and tail_kernel re-zeroes it at the end of every launch sequence.
__device__ int   g_cnt[NR];              // per-(rel,dst) edge counts
__device__ int   g_rowptr2[NR + 1];      // CSR row pointers, rel-major
__device__ int   g_woff[NR];             // working offsets for scatter
__device__ int   g_bsum[512];            // scan block sums
__device__ int   g_boff[512];            // scan block offsets
__device__ int2  g_emeta[DE];            // per-edge: .x = src | (dst<<16), .y = coef bits
__device__ float g_h[(size_t)DN * DD];   // layer-1 output
// weight tiles, tf32-rounded fp32, transposed layout [layer][chunk][n][k]
__device__ float g_wt[2 * NCHUNK * DD * DD];

__device__ __forceinline__ float to_tf32(float x) {
    float r;
    asm("cvt.rna.tf32.f32 %0, %1;" : "=f"(r) : "f"(x));
    return r;
}

// ---------------- preprocessing kernels ----------------
__global__ void count_kernel(const int* __restrict__ ei, const int* __restrict__ et, int E) {
    int e = blockIdx.x * blockDim.x + threadIdx.x;
    if (e < E) {
        int d = ei[E + e];
        int t = et[e];
        atomicAdd(&g_cnt[t * DN + d], 1);   // rel-major
    }
}

__global__ void scanA_kernel() {
    __shared__ int s[1024];
    int tid = threadIdx.x;
    int i = blockIdx.x * 1024 + tid;
    int v = (i < NR) ? g_cnt[i] : 0;
    s[tid] = v;
    __syncthreads();
    for (int off = 1; off < 1024; off <<= 1) {
        int t = (tid >= off) ? s[tid - off] : 0;
        __syncthreads();
        s[tid] += t;
        __syncthreads();
    }
    if (i < NR) g_rowptr2[i] = s[tid] - v;   // block-local exclusive
    if (tid == 1023) g_bsum[blockIdx.x] = s[1023];
}

__global__ void scanB_kernel(int nb) {
    __shared__ int s[512];
    int tid = threadIdx.x;
    int v = (tid < nb) ? g_bsum[tid] : 0;
    s[tid] = v;
    __syncthreads();
    for (int off = 1; off < 512; off <<= 1) {
        int t = (tid >= off) ? s[tid - off] : 0;
        __syncthreads();
        s[tid] += t;
        __syncthreads();
    }
    g_boff[tid] = s[tid] - v;   // exclusive
}

__global__ void scanC_kernel(int E) {
    int i = blockIdx.x * blockDim.x + threadIdx.x;
    if (i < NR) {
        int st = g_rowptr2[i] + g_boff[i >> 10];
        g_rowptr2[i] = st;
        g_woff[i] = st;
        if (i == 0) g_rowptr2[NR] = E;
    }
}

// merged: scatter (blocks [0,EB)) + weight prep (blocks [EB, EB+WB))
__global__ void scatter_wprep_kernel(
    const int* __restrict__ ei, const int* __restrict__ et, int E, int EB,
    const float* __restrict__ W1, const float* __restrict__ r1,
    const float* __restrict__ W2, const float* __restrict__ r2)
{
    int b = blockIdx.x;
    if (b < EB) {
        int e = b * 256 + threadIdx.x;
        if (e < E) {
            int s = ei[e];
            int d = ei[E + e];
            int t = et[e];
            int seg = t * DN + d;
            int pos = atomicAdd(&g_woff[seg], 1);
            int c = g_cnt[seg];
            float coef = 1.0f / (float)(c > 0 ? c : 1);
            g_emeta[pos] = make_int2((int)((unsigned)s | ((unsigned)d << 16)),
                                     __float_as_int(coef));
        }
    } else {
        int id = (b - EB) * 256 + threadIdx.x;
        const int total = 2 * NCHUNK * DD * DD;
        if (id < total) {
            int l   = id / (NCHUNK * DD * DD);
            int rem = id % (NCHUNK * DD * DD);
            int ch  = rem / (DD * DD);
            int pos = rem % (DD * DD);
            int n = pos >> 7, k = pos & 127;
            const float* W  = l ? W2 : W1;
            const float* rt = l ? r2 : r1;
            float wv = (ch < 8) ? W[((size_t)ch * DD + k) * DD + n] : rt[(size_t)k * DD + n];
            g_wt[id] = to_tf32(wv);
        }
    }
}

// tail: copy rel_emb to output AND re-zero g_cnt for the next replay
__global__ void tail_kernel(const float* __restrict__ rel, float* __restrict__ out) {
    int i = blockIdx.x * blockDim.x + threadIdx.x;
    if (i < DR * DD) out[i] = rel[i];
    for (int j = i; j < NR; j += gridDim.x * blockDim.x) g_cnt[j] = 0;
}

// ---------------- fused RGCN layer (tf32 mma, M-tile=64, 2 CTA/SM) ----------------
__device__ __forceinline__ void mma_tf32(float c[4],
    uint32_t a0, uint32_t a1, uint32_t a2, uint32_t a3,
    uint32_t b0, uint32_t b1)
{
    asm volatile(
        "mma.sync.aligned.m16n8k8.row.col.f32.tf32.tf32.f32 "
        "{%0,%1,%2,%3}, {%4,%5,%6,%7}, {%8,%9}, {%0,%1,%2,%3};\n"
        : "+f"(c[0]), "+f"(c[1]), "+f"(c[2]), "+f"(c[3])
        : "r"(a0), "r"(a1), "r"(a2), "r"(a3), "r"(b0), "r"(b1));
}

__device__ __forceinline__ void ldsm4(uint32_t& r0, uint32_t& r1, uint32_t& r2, uint32_t& r3,
                                      uint32_t addr)
{
    asm volatile("ldmatrix.sync.aligned.m8n8.x4.shared.b16 {%0,%1,%2,%3}, [%4];"
                 : "=r"(r0), "=r"(r1), "=r"(r2), "=r"(r3) : "r"(addr));
}

#define MT    64   // M tile (nodes per CTA)
#define PAD   132  // fp32 row stride (conflict-free frag loads)
#define SMEM_BYTES ((MT * PAD + 128 * PAD) * 4)   // A tile + B tile

__global__ __launch_bounds__(128, 2) void fused_layer_kernel(
    const float* __restrict__ X,
    const float* __restrict__ WT,    // layer base of g_wt
    const float* __restrict__ bias,
    float* __restrict__ out, int N)
{
    extern __shared__ char smem[];
    float* As = (float*)smem;            // MT x PAD fp32 (tf32-rounded)
    float* Bs = As + MT * PAD;           // 128 x PAD fp32 (tf32-rounded)

    const int tid  = threadIdx.x;
    const int w    = tid >> 5;           // 0..3
    const int lane = tid & 31;
    const int m0   = blockIdx.x * MT;
    const int warp_m = w >> 1;           // 0..1 (32 rows)
    const int warp_n = w & 1;            // 0..1 (64 cols)
    const int g = lane >> 2;             // 0..7
    const int t = lane & 3;              // 0..3

    float C[2][8][4];
    #pragma unroll
    for (int a = 0; a < 2; a++)
        #pragma unroll
        for (int b = 0; b < 8; b++)
            #pragma unroll
            for (int q = 0; q < 4; q++) C[a][b][q] = 0.0f;

    const int w16 = w * 16;              // this warp's 16 contiguous A rows

    // precomputed ldmatrix lane addresses (shared-space, bytes)
    uint32_t As_u = (uint32_t)__cvta_generic_to_shared(As);
    uint32_t Bs_u = (uint32_t)__cvta_generic_to_shared(Bs);
    uint32_t a_addr[2];
    #pragma unroll
    for (int mf = 0; mf < 2; mf++) {
        int r0m = warp_m * 32 + mf * 16;
        a_addr[mf] = As_u + (((r0m + (lane & 15)) * PAD) + ((lane >> 4) << 2)) * 4;
    }
    uint32_t b_addr[4];
    #pragma unroll
    for (int j = 0; j < 4; j++) {
        int n0 = warp_n * 64 + j * 16;
        b_addr[j] = Bs_u + (((n0 + (lane & 7) + ((lane & 16) >> 1)) * PAD)
                            + ((lane & 8) >> 1)) * 4;
    }

    for (int ch = 0; ch < NCHUNK; ch++) {
        __syncthreads();   // previous chunk's frag reads done; smem reusable

        // ---- B tile via cp.async.ca (L1-cached: co-resident CTA reuses) ----
        {
            const float* src = WT + ch * (DD * DD);
            #pragma unroll
            for (int v = 0; v < 32; v++) {
                int flat = v * 128 + tid;          // 4096 chunks of 4 floats
                int n  = flat >> 5;
                int kc = (flat & 31) << 2;
                uint32_t daddr = (uint32_t)__cvta_generic_to_shared(Bs + n * PAD + kc);
                asm volatile("cp.async.ca.shared.global [%0], [%1], 16;\n"
                             :: "r"(daddr), "l"(src + n * DD + kc));
            }
            asm volatile("cp.async.commit_group;\n");
        }

        // ---- build A tile (fp32) ----
        if (ch < 8) {
            // zero this warp's rows (exclusive ownership)
            #pragma unroll
            for (int i = 0; i < 16; i++)
                *(float4*)(As + (w16 + i) * PAD + lane * 4) =
                    make_float4(0.f, 0.f, 0.f, 0.f);

            int r0c = m0 + w16;      if (r0c > N) r0c = N;
            int r1c = m0 + w16 + 16; if (r1c > N) r1c = N;
            int wbeg = g_rowptr2[ch * DN + r0c];
            int wend = g_rowptr2[ch * DN + r1c];

            for (int e0 = wbeg; e0 < wend; e0 += 32) {
                int idx = e0 + lane;
                int2 mt = make_int2(0, 0);
                if (idx < wend) mt = g_emeta[idx];
                int cnt = wend - e0; if (cnt > 32) cnt = 32;
                for (int j = 0; j < cnt; j += 8) {
                    int nb = cnt - j; if (nb > 8) nb = 8;
                    int pk[8]; float cc[8]; float4 v[8];
                    #pragma unroll
                    for (int q = 0; q < 8; q++) {
                        pk[q] = __shfl_sync(FULLM, mt.x, j + q);
                        cc[q] = __shfl_sync(FULLM, __int_as_float(mt.y), j + q);
                    }
                    #pragma unroll
                    for (int q = 0; q < 8; q++)
                        if (q < nb)
                            v[q] = *(const float4*)(X +
                                   (size_t)((unsigned)pk[q] & 0xffffu) * DD + lane * 4);
                    #pragma unroll
                    for (int q = 0; q < 8; q++)
                        if (q < nb) {
                            int dl = (int)(((unsigned)pk[q]) >> 16) - m0;
                            float* rp = As + dl * PAD + lane * 4;
                            float4 cur = *(float4*)rp;
                            cur.x += cc[q] * v[q].x;
                            cur.y += cc[q] * v[q].y;
                            cur.z += cc[q] * v[q].z;
                            cur.w += cc[q] * v[q].w;
                            *(float4*)rp = cur;
                        }
                }
            }
            // tf32-round this warp's rows in place
            #pragma unroll
            for (int i = 0; i < 16; i++) {
                float* rp = As + (w16 + i) * PAD + lane * 4;
                float4 vv = *(float4*)rp;
                vv.x = to_tf32(vv.x); vv.y = to_tf32(vv.y);
                vv.z = to_tf32(vv.z); vv.w = to_tf32(vv.w);
                *(float4*)rp = vv;
            }
        } else {
            // root chunk: A = X tile (tf32-rounded)
            #pragma unroll
            for (int i = 0; i < 16; i++) {
                int row  = w16 + i;
                int node = m0 + row;
                float4 v = make_float4(0.f, 0.f, 0.f, 0.f);
                if (node < N) v = *(const float4*)(X + (size_t)node * DD + lane * 4);
                v.x = to_tf32(v.x); v.y = to_tf32(v.y);
                v.z = to_tf32(v.z); v.w = to_tf32(v.w);
                *(float4*)(As + row * PAD + lane * 4) = v;
            }
        }
        asm volatile("cp.async.wait_group 0;\n" ::: "memory");
        __syncthreads();

        // ---- MMA: 16 k-steps of m16n8k8 tf32, frag loads via ldmatrix ----
        #pragma unroll
        for (int ks = 0; ks < 16; ks++) {
            uint32_t koff = ks * 32;   // 8 floats * 4B
            uint32_t bf[8][2];
            #pragma unroll
            for (int j = 0; j < 4; j++) {
                ldsm4(bf[2*j][0], bf[2*j][1], bf[2*j+1][0], bf[2*j+1][1],
                      b_addr[j] + koff);
            }
            uint32_t af[2][4];
            #pragma unroll
            for (int mf = 0; mf < 2; mf++)
                ldsm4(af[mf][0], af[mf][1], af[mf][2], af[mf][3],
                      a_addr[mf] + koff);
            #pragma unroll
            for (int mf = 0; mf < 2; mf++)
                #pragma unroll
                for (int nf = 0; nf < 8; nf++)
                    mma_tf32(C[mf][nf], af[mf][0], af[mf][1], af[mf][2], af[mf][3],
                             bf[nf][0], bf[nf][1]);
        }
    }

    // ---- epilogue: + bias, ReLU ----
    #pragma unroll
    for (int mf = 0; mf < 2; mf++)
        #pragma unroll
        for (int nf = 0; nf < 8; nf++) {
            int row = warp_m * 32 + mf * 16 + g;
            int col = warp_n * 64 + nf * 8 + 2 * t;
            float b0 = bias[col], b1 = bias[col + 1];
            int node0 = m0 + row;
            if (node0 < N) {
                float o0 = C[mf][nf][0] + b0; o0 = o0 > 0.f ? o0 : 0.f;
                float o1 = C[mf][nf][1] + b1; o1 = o1 > 0.f ? o1 : 0.f;
                *(float2*)(out + (size_t)node0 * DD + col) = make_float2(o0, o1);
            }
            int node1 = m0 + row + 8;
            if (node1 < N) {
                float o2 = C[mf][nf][2] + b0; o2 = o2 > 0.f ? o2 : 0.f;
                float o3 = C[mf][nf][3] + b1; o3 = o3 > 0.f ? o3 : 0.f;
                *(float2*)(out + (size_t)node1 * DD + col) = make_float2(o2, o3);
            }
        }
}

// ---------------- launch ----------------
extern "C" void kernel_launch(void* const* d_in, const int* in_sizes, int n_in,
                              void* d_out, int out_size) {
    const float* x     = (const float*)d_in[0];
    const int*   ei    = (const int*)d_in[1];
    const int*   et    = (const int*)d_in[2];
    const float* W1    = (const float*)d_in[3];
    const float* root1 = (const float*)d_in[4];
    const float* b1    = (const float*)d_in[5];
    const float* W2    = (const float*)d_in[6];
    const float* root2 = (const float*)d_in[7];
    const float* b2    = (const float*)d_in[8];
    const float* rel   = (const float*)d_in[9];

    const int N = in_sizes[0] / DD;   // 50000
    const int E = in_sizes[2];        // 600000

    float* h1;  cudaGetSymbolAddress((void**)&h1, g_h);
    float* wt;  cudaGetSymbolAddress((void**)&wt, g_wt);

    float* out_h   = (float*)d_out;
    float* out_rel = (float*)d_out + (size_t)N * DD;

    static int smem_set = 0;
    if (!smem_set) {
        cudaFuncSetAttribute(fused_layer_kernel,
                             cudaFuncAttributeMaxDynamicSharedMemorySize, SMEM_BYTES);
        smem_set = 1;
    }

    // ---- preprocessing (5 launches; g_cnt pre-zeroed by tail of prior run) ----
    count_kernel<<<(E + 255) / 256, 256>>>(ei, et, E);            // launch 1
    const int nb = (NR + 1023) / 1024;   // 391
    scanA_kernel<<<nb, 1024>>>();                                  // launch 2
    scanB_kernel<<<1, 512>>>(nb);                                  // launch 3
    scanC_kernel<<<(NR + 255) / 256, 256>>>(E);                    // launch 4
    const int EB = (E + 255) / 256;
    const int WB = (2 * NCHUNK * DD * DD + 255) / 256;
    scatter_wprep_kernel<<<EB + WB, 256>>>(ei, et, E, EB,
                                           W1, root1, W2, root2);  // launch 5

    const int grid = (N + MT - 1) / MT;   // 782

    // ---- layer 1 (launch 6 — ncu -s 5 profiles this) ----
    fused_layer_kernel<<<grid, 128, SMEM_BYTES>>>(x, wt, b1, h1, N);
    // ---- layer 2 ----
    fused_layer_kernel<<<grid, 128, SMEM_BYTES>>>(h1, wt + NCHUNK * DD * DD, b2, out_h, N);

    // ---- tail: rel_emb copy + re-zero g_cnt for next replay ----
    tail_kernel<<<400, 1024>>>(rel, out_rel);
}